// round 6
// baseline (speedup 1.0000x reference)
#include <cuda_runtime.h>
#include <cstdint>

#define N_NODES 100000
#define N_EDGES 1600000
#define IN_DIM  256
#define OUT_DIM 64

#define GEMM_BLOCKS ((N_NODES + 255) / 256)   // 391
#define SCAN_BLK    98                        // ceil(100000 / 1024)
#define SCAN_CHUNK  1024

// Scratch (device globals; g_cnt starts zeroed and is self-reset each run).
__device__ float               g_X[(size_t)N_NODES * OUT_DIM];
__device__ int                 g_cnt[N_NODES];
__device__ int                 g_offs[N_NODES + 1];
__device__ int                 g_cursor[N_NODES];
__device__ int                 g_sorted_cols[N_EDGES];
__device__ unsigned long long  g_state[SCAN_BLK];   // packed (sum<<2)|flag

// ---------------------------------------------------------------------------
// Launch 1: fused GEMM + edge histogram + scan-state zeroing.
// GEMM: X = inputs @ W via packed fma.rn.f32x2 (thread: 4 rows x 16 cols).
// ---------------------------------------------------------------------------
__global__ __launch_bounds__(256) void gemmhist_kernel(
    const float* __restrict__ in, const float* __restrict__ w,
    const int* __restrict__ rows)
{
    // Zero decoupled-lookback states for this run (read by scan_kernel later).
    if (blockIdx.x == 0) {
        for (int i = threadIdx.x; i < SCAN_BLK; i += 256)
            g_state[i] = 0ULL;
    }

    // Edge histogram, grid-stride. REDs drain asynchronously under the GEMM.
    for (int e = blockIdx.x * 256 + threadIdx.x; e < N_EDGES;
         e += GEMM_BLOCKS * 256)
        atomicAdd(&g_cnt[rows[e]], 1);

    __shared__ float sw[IN_DIM * OUT_DIM];  // 64 KB
    {
        const float4* wsrc = (const float4*)w;
        float4* wdst = (float4*)sw;
        #pragma unroll
        for (int i = 0; i < 16; i++)
            wdst[threadIdx.x + i * 256] = wsrc[threadIdx.x + i * 256];
    }
    __syncthreads();

    const int colg = threadIdx.x & 3;
    const int rowg = threadIdx.x >> 2;
    const int row0 = blockIdx.x * 256 + rowg * 4;

    int r[4];
    #pragma unroll
    for (int i = 0; i < 4; i++) {
        int rr = row0 + i;
        r[i] = rr < N_NODES ? rr : (N_NODES - 1);
    }

    const float4* inp[4];
    #pragma unroll
    for (int i = 0; i < 4; i++)
        inp[i] = (const float4*)(in + (size_t)r[i] * IN_DIM);

    unsigned long long acc[4][8];
    #pragma unroll
    for (int i = 0; i < 4; i++)
        #pragma unroll
        for (int j = 0; j < 8; j++) acc[i][j] = 0ULL;

    #pragma unroll 2
    for (int k4 = 0; k4 < IN_DIM / 4; k4++) {
        float4 a4[4];
        #pragma unroll
        for (int i = 0; i < 4; i++) a4[i] = inp[i][k4];

        #pragma unroll
        for (int kk = 0; kk < 4; kk++) {
            const int k = k4 * 4 + kk;
            const ulonglong2* wrow =
                (const ulonglong2*)(sw + k * OUT_DIM + colg * 16);
            unsigned long long wp[8];
            #pragma unroll
            for (int j = 0; j < 4; j++) {
                ulonglong2 v = wrow[j];
                wp[2 * j]     = v.x;
                wp[2 * j + 1] = v.y;
            }
            #pragma unroll
            for (int i = 0; i < 4; i++) {
                float a = (kk == 0) ? a4[i].x : (kk == 1) ? a4[i].y
                        : (kk == 2) ? a4[i].z : a4[i].w;
                unsigned long long av;
                asm("mov.b64 %0, {%1,%1};" : "=l"(av) : "f"(a));
                #pragma unroll
                for (int j = 0; j < 8; j++)
                    asm("fma.rn.f32x2 %0, %1, %2, %0;"
                        : "+l"(acc[i][j]) : "l"(av), "l"(wp[j]));
            }
        }
    }

    #pragma unroll
    for (int i = 0; i < 4; i++) {
        int rr = row0 + i;
        if (rr < N_NODES) {
            ulonglong2* dst =
                (ulonglong2*)(g_X + (size_t)rr * OUT_DIM + colg * 16);
            dst[0] = make_ulonglong2(acc[i][0], acc[i][1]);
            dst[1] = make_ulonglong2(acc[i][2], acc[i][3]);
            dst[2] = make_ulonglong2(acc[i][4], acc[i][5]);
            dst[3] = make_ulonglong2(acc[i][6], acc[i][7]);
        }
    }
}

// ---------------------------------------------------------------------------
// Launch 2: single-pass exclusive scan (decoupled lookback), 98 blocks.
// flag: 0 = empty, 1 = partial (local sum), 2 = done (inclusive prefix).
// ---------------------------------------------------------------------------
__global__ __launch_bounds__(256) void scan_kernel()
{
    __shared__ int part[256];
    __shared__ int sbase;
    const int t = threadIdx.x;
    const int b = blockIdx.x;
    const int i0 = b * SCAN_CHUNK + t * 4;

    int c[4];
    int s = 0;
    #pragma unroll
    for (int j = 0; j < 4; j++) {
        c[j] = (i0 + j < N_NODES) ? g_cnt[i0 + j] : 0;
        s += c[j];
    }
    part[t] = s;
    __syncthreads();
    #pragma unroll
    for (int d = 1; d < 256; d <<= 1) {
        int u = (t >= d) ? part[t - d] : 0;
        __syncthreads();
        part[t] += u;
        __syncthreads();
    }
    const int total = part[255];

    // Publish local sum ASAP (block 0 publishes DONE immediately).
    if (t == 0) {
        unsigned long long packed =
            ((unsigned long long)total << 2) | (b == 0 ? 2ULL : 1ULL);
        atomicExch(&g_state[b], packed);
        if (b == 0) sbase = 0;
    }

    // Warp 0 lookback (b > 0): walk predecessors 32 at a time.
    if (b > 0 && t < 32) {
        int base = 0;
        int p = b - 1;
        while (true) {
            const int i = p - t;
            unsigned long long st;
            if (i >= 0) {
                do {
                    st = atomicAdd(&g_state[i], 0ULL);
                } while ((st & 3ULL) == 0ULL);
            } else {
                st = 2ULL;  // virtual DONE with value 0
            }
            const int flag = (int)(st & 3ULL);
            const int val  = (int)(st >> 2);
            const unsigned dm = __ballot_sync(0xFFFFFFFFu, flag == 2);
            int contrib;
            if (dm) {
                const int fd = __ffs(dm) - 1;  // nearest DONE
                contrib = (t <= fd) ? val : 0;
            } else {
                contrib = val;                  // all partial: take all
            }
            #pragma unroll
            for (int d = 16; d > 0; d >>= 1)
                contrib += __shfl_down_sync(0xFFFFFFFFu, contrib, d);
            contrib = __shfl_sync(0xFFFFFFFFu, contrib, 0);
            base += contrib;
            if (dm) break;
            p -= 32;
        }
        if (t == 0) {
            sbase = base;
            atomicExch(&g_state[b],
                       ((unsigned long long)(base + total) << 2) | 2ULL);
        }
    }
    __syncthreads();

    int run = sbase + part[t] - s;  // exclusive prefix for this thread's 4
    #pragma unroll
    for (int j = 0; j < 4; j++) {
        if (i0 + j < N_NODES) {
            g_offs[i0 + j] = run;
            g_cursor[i0 + j] = run;
        }
        run += c[j];
    }
    if (b == 0 && t == 0) g_offs[N_NODES] = N_EDGES;
}

// ---------------------------------------------------------------------------
// Launch 3: bucket fill (counting sort of cols by destination row).
// ---------------------------------------------------------------------------
__global__ __launch_bounds__(256) void fill_kernel(
    const int* __restrict__ rows, const int* __restrict__ cols)
{
    int e = blockIdx.x * blockDim.x + threadIdx.x;
    if (e < N_EDGES) {
        int r = rows[e];
        int pos = atomicAdd(&g_cursor[r], 1);
        g_sorted_cols[pos] = cols[e];
    }
}

// ---------------------------------------------------------------------------
// Launch 4 (PROFILED): CSR aggregation + fused sigmoid.
// Half-warp per node, lane owns a float4. Unroll-8: all 8 gathers issued
// before accumulation (MLP=8). Resets g_cnt for the next replay.
// ---------------------------------------------------------------------------
__global__ __launch_bounds__(256) void aggregate_kernel(float* __restrict__ out)
{
    const int hw   = threadIdx.x >> 4;
    const int hl   = threadIdx.x & 15;
    const int node = blockIdx.x * 16 + hw;
    if (node >= N_NODES) return;

    const int start = g_offs[node];
    const int end   = g_offs[node + 1];
    if (hl == 0) g_cnt[node] = 0;  // reset histogram for next run

    const float* Xl = g_X + hl * 4;

    float4 A = make_float4(0.f, 0.f, 0.f, 0.f);
    float4 B = make_float4(0.f, 0.f, 0.f, 0.f);

    int idx = start;
    for (; idx + 8 <= end; idx += 8) {
        int c[8];
        #pragma unroll
        for (int j = 0; j < 8; j++) c[j] = __ldg(&g_sorted_cols[idx + j]);
        float4 v[8];
        #pragma unroll
        for (int j = 0; j < 8; j++)
            v[j] = __ldg((const float4*)(Xl + (size_t)c[j] * OUT_DIM));
        #pragma unroll
        for (int j = 0; j < 8; j += 2) {
            A.x += v[j].x;     A.y += v[j].y;
            A.z += v[j].z;     A.w += v[j].w;
            B.x += v[j + 1].x; B.y += v[j + 1].y;
            B.z += v[j + 1].z; B.w += v[j + 1].w;
        }
    }
    for (; idx + 2 <= end; idx += 2) {
        const int c0 = __ldg(&g_sorted_cols[idx]);
        const int c1 = __ldg(&g_sorted_cols[idx + 1]);
        const float4 v0 = __ldg((const float4*)(Xl + (size_t)c0 * OUT_DIM));
        const float4 v1 = __ldg((const float4*)(Xl + (size_t)c1 * OUT_DIM));
        A.x += v0.x; A.y += v0.y; A.z += v0.z; A.w += v0.w;
        B.x += v1.x; B.y += v1.y; B.z += v1.z; B.w += v1.w;
    }
    if (idx < end) {
        const int c = __ldg(&g_sorted_cols[idx]);
        const float4 v = __ldg((const float4*)(Xl + (size_t)c * OUT_DIM));
        A.x += v.x; A.y += v.y; A.z += v.z; A.w += v.w;
    }
    A.x += B.x; A.y += B.y; A.z += B.z; A.w += B.w;

    float4 o;
    o.x = 1.0f / (1.0f + __expf(-A.x));
    o.y = 1.0f / (1.0f + __expf(-A.y));
    o.z = 1.0f / (1.0f + __expf(-A.z));
    o.w = 1.0f / (1.0f + __expf(-A.w));
    *(float4*)(out + (size_t)node * OUT_DIM + hl * 4) = o;
}

extern "C" void kernel_launch(void* const* d_in, const int* in_sizes, int n_in,
                              void* d_out, int out_size)
{
    const float* inputs = (const float*)d_in[0];   // [100000, 256] f32
    const int*   eidx   = (const int*)d_in[1];     // [2, 1600000] int32
    const float* weight = (const float*)d_in[2];   // [256, 64] f32
    float*       out    = (float*)d_out;           // [100000, 64] f32

    const int* erows = eidx;
    const int* ecols = eidx + N_EDGES;

    gemmhist_kernel<<<GEMM_BLOCKS, 256>>>(inputs, weight, erows);   // 1
    scan_kernel<<<SCAN_BLK, 256>>>();                               // 2
    fill_kernel<<<(N_EDGES + 255) / 256, 256>>>(erows, ecols);      // 3
    aggregate_kernel<<<(N_NODES + 15) / 16, 256>>>(out);            // 4 (profiled)
}